// round 4
// baseline (speedup 1.0000x reference)
#include <cuda_runtime.h>
#include <cstdint>

#define NF      32
#define NPOLY   6545
#define BATCH   8192
#define KC      64          // K-chunk (poly features per smem tile)
#define ROWS    64          // batch rows per CTA
#define RPAIRS  32          // ROWS/2 row-pairs (f32x2 packing)
#define THREADS 256
#define NWARP   8
#define RPW     4           // row-pairs per warp

// Packed index table: poly[p] = x[a]*x[b]*x[c]; index 32 -> constant 1.0 slot.
__device__ uint32_t g_idx[NPOLY];

// ---------------------------------------------------------------------------
// Build the monomial index table (Pascal-triangle recursion flattened).
// p=0: 1 ; p in [1,33): x_{p-1} ; p in [33,561): x_f*x_m (m<=f) ;
// p in [561,6545): x_f*x_g*x_m (m<=g<=f), f-major / triangular inner order —
// exactly the reference's level ordering. Value computed as a*(b*c) to
// bit-match the reference's x_f * prev rounding.
// ---------------------------------------------------------------------------
__global__ void build_idx_kernel() {
    int p = blockIdx.x * blockDim.x + threadIdx.x;
    if (p >= NPOLY) return;
    int a = 32, b = 32, c = 32;
    if (p == 0) {
        // all ones
    } else if (p < 33) {
        a = p - 1;
    } else if (p < 561) {
        int q = p - 33;
        int f = (int)((sqrtf(8.0f * (float)q + 1.0f) - 1.0f) * 0.5f);
        if (f < 0) f = 0; if (f > 31) f = 31;
        while (f < 31 && (f + 1) * (f + 2) / 2 <= q) f++;
        while (f > 0 && f * (f + 1) / 2 > q) f--;
        a = f;
        b = q - f * (f + 1) / 2;
    } else {
        int q = p - 561;
        int f = (int)cbrtf(6.0f * (float)q);
        if (f < 0) f = 0; if (f > 31) f = 31;
        while (f < 31 && (f + 1) * (f + 2) * (f + 3) / 6 <= q) f++;
        while (f > 0 && f * (f + 1) * (f + 2) / 6 > q) f--;
        int r = q - f * (f + 1) * (f + 2) / 6;
        int g = (int)((sqrtf(8.0f * (float)r + 1.0f) - 1.0f) * 0.5f);
        if (g < 0) g = 0; if (g > f) g = f;
        while (g < f && (g + 1) * (g + 2) / 2 <= r) g++;
        while (g > 0 && g * (g + 1) / 2 > r) g--;
        a = f;
        b = g;
        c = r - g * (g + 1) / 2;
    }
    g_idx[p] = (uint32_t)a | ((uint32_t)b << 8) | ((uint32_t)c << 16);
}

// packed f32x2 FMA: d = a*b + d  (2 FMAs per instruction; ptxas never emits
// FFMA2 from C++ — PTX-only path per sm_103a SASS reference)
__device__ __forceinline__ void fma2(unsigned long long& d,
                                     unsigned long long a,
                                     unsigned long long b) {
    asm("fma.rn.f32x2 %0, %1, %2, %0;" : "+l"(d) : "l"(a), "l"(b));
}

__device__ __forceinline__ unsigned long long pack2(float lo, float hi) {
    unsigned long long r;
    asm("mov.b64 %0, {%1, %2};" : "=l"(r) : "f"(lo), "f"(hi));
    return r;
}

// ---------------------------------------------------------------------------
// Fused TaylorMap: per CTA 64 rows, loop K in chunks of 64.
//   phase A: stage W chunk + generate poly chunk (row-paired float2) in smem
//   phase B: each warp owns 4 row-pairs, lane = output column; f32x2 FMA
// ---------------------------------------------------------------------------
__global__ __launch_bounds__(THREADS)
void taylor_kernel(const float* __restrict__ x,
                   const float* __restrict__ W,
                   float* __restrict__ out) {
    // polyS MUST be 16B-aligned: the accumulate phase reads it with LDS.128
    // (ulonglong2). Default float2 alignment is 8 and xt's size is 8 mod 16,
    // which is exactly the R1 "misaligned address" trap.
    __shared__ __align__(16) float2 polyS[RPAIRS][KC];   // 16 KB
    __shared__ __align__(16) float  wS[KC][NF];          // 8 KB
    __shared__ float  xt[33][ROWS + 2];                  // 8.7 KB

    const int tid  = threadIdx.x;
    const int lane = tid & 31;
    const int warp = tid >> 5;
    const int row0 = blockIdx.x * ROWS;

    // load x tile transposed: xt[i][r]; i==32 is the constant-1 slot
    for (int e = tid; e < ROWS * 33; e += THREADS) {
        int r = e / 33;
        int i = e - r * 33;
        xt[i][r] = (i < NF) ? x[(row0 + r) * NF + i] : 1.0f;
    }

    // accumulators: 4 row-pairs per warp, init with residual x
    unsigned long long acc[RPW];
    const int rbase = warp * (2 * RPW);   // first row of this warp
#pragma unroll
    for (int i = 0; i < RPW; i++) {
        int r0 = row0 + rbase + 2 * i;
        acc[i] = pack2(x[r0 * NF + lane], x[(r0 + 1) * NF + lane]);
    }

    for (int k0 = 0; k0 < NPOLY; k0 += KC) {
        __syncthreads();   // previous accum done before overwriting smem

        // ---- stage W chunk (zero-fill tail so garbage never enters FMA) ----
        for (int e = tid; e < KC * NF; e += THREADS) {
            int k = e >> 5, j = e & 31;
            int kg = k0 + k;
            wS[k][j] = (kg < NPOLY) ? W[kg * NF + j] : 0.0f;
        }

        // ---- generate poly chunk -------------------------------------------
        // item = (row-pair rp, 32-wide k block); lane = k offset, so STS.64
        // hits 32 consecutive float2 (conflict-free).
        for (int it = warp; it < RPAIRS * (KC / 32); it += NWARP) {
            int rp = it >> 1;
            int k  = ((it & 1) << 5) + lane;
            int kg = k0 + k;
            float2 v;
            if (kg < NPOLY) {
                uint32_t id = g_idx[kg];
                int a =  id        & 255;
                int b = (id >> 8)  & 255;
                int c = (id >> 16) & 255;
                float2 fa = *(const float2*)&xt[a][2 * rp];
                float2 fb = *(const float2*)&xt[b][2 * rp];
                float2 fc = *(const float2*)&xt[c][2 * rp];
                float t0 = fb.x * fc.x;      // matches reference rounding order
                float t1 = fb.y * fc.y;
                v.x = fa.x * t0;
                v.y = fa.y * t1;
            } else {
                v.x = 0.0f; v.y = 0.0f;
            }
            polyS[rp][k] = v;
        }
        __syncthreads();

        // ---- accumulate -----------------------------------------------------
#pragma unroll 4
        for (int ks = 0; ks < KC; ks += 4) {
            unsigned long long wp0, wp1, wp2, wp3;
            {
                float w0 = wS[ks + 0][lane];
                float w1 = wS[ks + 1][lane];
                float w2 = wS[ks + 2][lane];
                float w3 = wS[ks + 3][lane];
                asm("mov.b64 %0, {%1, %1};" : "=l"(wp0) : "f"(w0));
                asm("mov.b64 %0, {%1, %1};" : "=l"(wp1) : "f"(w1));
                asm("mov.b64 %0, {%1, %1};" : "=l"(wp2) : "f"(w2));
                asm("mov.b64 %0, {%1, %1};" : "=l"(wp3) : "f"(w3));
            }
#pragma unroll
            for (int i = 0; i < RPW; i++) {
                int rp = warp * RPW + i;
                const float2* pr = &polyS[rp][ks];
                ulonglong2 q0 = *(const ulonglong2*)(pr);       // k=ks, ks+1
                ulonglong2 q1 = *(const ulonglong2*)(pr + 2);   // k=ks+2, ks+3
                fma2(acc[i], q0.x, wp0);
                fma2(acc[i], q0.y, wp1);
                fma2(acc[i], q1.x, wp2);
                fma2(acc[i], q1.y, wp3);
            }
        }
    }

    // ---- write out ----------------------------------------------------------
#pragma unroll
    for (int i = 0; i < RPW; i++) {
        int r0 = row0 + rbase + 2 * i;
        float lo, hi;
        asm("mov.b64 {%0, %1}, %2;" : "=f"(lo), "=f"(hi) : "l"(acc[i]));
        out[r0 * NF + lane]       = lo;
        out[(r0 + 1) * NF + lane] = hi;
    }
}

extern "C" void kernel_launch(void* const* d_in, const int* in_sizes, int n_in,
                              void* d_out, int out_size) {
    const float* x = (const float*)d_in[0];
    const float* W = (const float*)d_in[1];
    // defensive: identify tensors by element count in case of ordering drift
    if (n_in >= 2 && in_sizes[0] == NPOLY * NF && in_sizes[1] == BATCH * NF) {
        x = (const float*)d_in[1];
        W = (const float*)d_in[0];
    }
    float* out = (float*)d_out;

    build_idx_kernel<<<(NPOLY + 255) / 256, 256>>>();
    taylor_kernel<<<BATCH / ROWS, THREADS>>>(x, W, out);
}

// round 5
// speedup vs baseline: 1.0022x; 1.0022x over previous
#include <cuda_runtime.h>
#include <cstdint>

#define NF      32
#define NPOLY   6545
#define BATCH   8192
#define KC      64          // K-chunk (poly features per smem tile)
#define ROWS    64          // batch rows per CTA
#define RPAIRS  32          // ROWS/2 row-pairs (f32x2 packing)
#define THREADS 256
#define NWARP   8
#define RPW     4           // row-pairs per warp

// Packed index table: poly[p] = x[a]*x[b]*x[c]; index 32 -> constant 1.0 slot.
__device__ uint32_t g_idx[NPOLY];

// ---------------------------------------------------------------------------
// Build the monomial index table (Pascal-triangle recursion flattened).
// p=0: 1 ; p in [1,33): x_{p-1} ; p in [33,561): x_f*x_m (m<=f) ;
// p in [561,6545): x_f*x_g*x_m (m<=g<=f), f-major / triangular inner order —
// exactly the reference's level ordering. Value computed as a*(b*c) to
// bit-match the reference's x_f * prev rounding.
// ---------------------------------------------------------------------------
__global__ void build_idx_kernel() {
    int p = blockIdx.x * blockDim.x + threadIdx.x;
    if (p >= NPOLY) return;
    int a = 32, b = 32, c = 32;
    if (p == 0) {
        // all ones
    } else if (p < 33) {
        a = p - 1;
    } else if (p < 561) {
        int q = p - 33;
        int f = (int)((sqrtf(8.0f * (float)q + 1.0f) - 1.0f) * 0.5f);
        if (f < 0) f = 0; if (f > 31) f = 31;
        while (f < 31 && (f + 1) * (f + 2) / 2 <= q) f++;
        while (f > 0 && f * (f + 1) / 2 > q) f--;
        a = f;
        b = q - f * (f + 1) / 2;
    } else {
        int q = p - 561;
        int f = (int)cbrtf(6.0f * (float)q);
        if (f < 0) f = 0; if (f > 31) f = 31;
        while (f < 31 && (f + 1) * (f + 2) * (f + 3) / 6 <= q) f++;
        while (f > 0 && f * (f + 1) * (f + 2) / 6 > q) f--;
        int r = q - f * (f + 1) * (f + 2) / 6;
        int g = (int)((sqrtf(8.0f * (float)r + 1.0f) - 1.0f) * 0.5f);
        if (g < 0) g = 0; if (g > f) g = f;
        while (g < f && (g + 1) * (g + 2) / 2 <= r) g++;
        while (g > 0 && g * (g + 1) / 2 > r) g--;
        a = f;
        b = g;
        c = r - g * (g + 1) / 2;
    }
    g_idx[p] = (uint32_t)a | ((uint32_t)b << 8) | ((uint32_t)c << 16);
}

// packed f32x2 FMA: d = a*b + d  (2 FMAs per instruction; ptxas never emits
// FFMA2 from C++ — PTX-only path per sm_103a SASS reference)
__device__ __forceinline__ void fma2(unsigned long long& d,
                                     unsigned long long a,
                                     unsigned long long b) {
    asm("fma.rn.f32x2 %0, %1, %2, %0;" : "+l"(d) : "l"(a), "l"(b));
}

__device__ __forceinline__ unsigned long long pack2(float lo, float hi) {
    unsigned long long r;
    asm("mov.b64 %0, {%1, %2};" : "=l"(r) : "f"(lo), "f"(hi));
    return r;
}

// ---------------------------------------------------------------------------
// Fused TaylorMap: per CTA 64 rows, loop K in chunks of 64.
//   phase A: stage W chunk + generate poly chunk (row-paired float2) in smem
//   phase B: each warp owns 4 row-pairs, lane = output column; f32x2 FMA
// ---------------------------------------------------------------------------
__global__ __launch_bounds__(THREADS)
void taylor_kernel(const float* __restrict__ x,
                   const float* __restrict__ W,
                   float* __restrict__ out) {
    // polyS MUST be 16B-aligned: the accumulate phase reads it with LDS.128
    // (ulonglong2). Default float2 alignment is 8 and xt's size is 8 mod 16,
    // which is exactly the R1 "misaligned address" trap.
    __shared__ __align__(16) float2 polyS[RPAIRS][KC];   // 16 KB
    __shared__ __align__(16) float  wS[KC][NF];          // 8 KB
    __shared__ float  xt[33][ROWS + 2];                  // 8.7 KB

    const int tid  = threadIdx.x;
    const int lane = tid & 31;
    const int warp = tid >> 5;
    const int row0 = blockIdx.x * ROWS;

    // load x tile transposed: xt[i][r]; i==32 is the constant-1 slot
    for (int e = tid; e < ROWS * 33; e += THREADS) {
        int r = e / 33;
        int i = e - r * 33;
        xt[i][r] = (i < NF) ? x[(row0 + r) * NF + i] : 1.0f;
    }

    // accumulators: 4 row-pairs per warp, init with residual x
    unsigned long long acc[RPW];
    const int rbase = warp * (2 * RPW);   // first row of this warp
#pragma unroll
    for (int i = 0; i < RPW; i++) {
        int r0 = row0 + rbase + 2 * i;
        acc[i] = pack2(x[r0 * NF + lane], x[(r0 + 1) * NF + lane]);
    }

    for (int k0 = 0; k0 < NPOLY; k0 += KC) {
        __syncthreads();   // previous accum done before overwriting smem

        // ---- stage W chunk (zero-fill tail so garbage never enters FMA) ----
        for (int e = tid; e < KC * NF; e += THREADS) {
            int k = e >> 5, j = e & 31;
            int kg = k0 + k;
            wS[k][j] = (kg < NPOLY) ? W[kg * NF + j] : 0.0f;
        }

        // ---- generate poly chunk -------------------------------------------
        // item = (row-pair rp, 32-wide k block); lane = k offset, so STS.64
        // hits 32 consecutive float2 (conflict-free).
        for (int it = warp; it < RPAIRS * (KC / 32); it += NWARP) {
            int rp = it >> 1;
            int k  = ((it & 1) << 5) + lane;
            int kg = k0 + k;
            float2 v;
            if (kg < NPOLY) {
                uint32_t id = g_idx[kg];
                int a =  id        & 255;
                int b = (id >> 8)  & 255;
                int c = (id >> 16) & 255;
                float2 fa = *(const float2*)&xt[a][2 * rp];
                float2 fb = *(const float2*)&xt[b][2 * rp];
                float2 fc = *(const float2*)&xt[c][2 * rp];
                float t0 = fb.x * fc.x;      // matches reference rounding order
                float t1 = fb.y * fc.y;
                v.x = fa.x * t0;
                v.y = fa.y * t1;
            } else {
                v.x = 0.0f; v.y = 0.0f;
            }
            polyS[rp][k] = v;
        }
        __syncthreads();

        // ---- accumulate -----------------------------------------------------
#pragma unroll 4
        for (int ks = 0; ks < KC; ks += 4) {
            unsigned long long wp0, wp1, wp2, wp3;
            {
                float w0 = wS[ks + 0][lane];
                float w1 = wS[ks + 1][lane];
                float w2 = wS[ks + 2][lane];
                float w3 = wS[ks + 3][lane];
                asm("mov.b64 %0, {%1, %1};" : "=l"(wp0) : "f"(w0));
                asm("mov.b64 %0, {%1, %1};" : "=l"(wp1) : "f"(w1));
                asm("mov.b64 %0, {%1, %1};" : "=l"(wp2) : "f"(w2));
                asm("mov.b64 %0, {%1, %1};" : "=l"(wp3) : "f"(w3));
            }
#pragma unroll
            for (int i = 0; i < RPW; i++) {
                int rp = warp * RPW + i;
                const float2* pr = &polyS[rp][ks];
                ulonglong2 q0 = *(const ulonglong2*)(pr);       // k=ks, ks+1
                ulonglong2 q1 = *(const ulonglong2*)(pr + 2);   // k=ks+2, ks+3
                fma2(acc[i], q0.x, wp0);
                fma2(acc[i], q0.y, wp1);
                fma2(acc[i], q1.x, wp2);
                fma2(acc[i], q1.y, wp3);
            }
        }
    }

    // ---- write out ----------------------------------------------------------
#pragma unroll
    for (int i = 0; i < RPW; i++) {
        int r0 = row0 + rbase + 2 * i;
        float lo, hi;
        asm("mov.b64 {%0, %1}, %2;" : "=f"(lo), "=f"(hi) : "l"(acc[i]));
        out[r0 * NF + lane]       = lo;
        out[(r0 + 1) * NF + lane] = hi;
    }
}

extern "C" void kernel_launch(void* const* d_in, const int* in_sizes, int n_in,
                              void* d_out, int out_size) {
    const float* x = (const float*)d_in[0];
    const float* W = (const float*)d_in[1];
    // defensive: identify tensors by element count in case of ordering drift
    if (n_in >= 2 && in_sizes[0] == NPOLY * NF && in_sizes[1] == BATCH * NF) {
        x = (const float*)d_in[1];
        W = (const float*)d_in[0];
    }
    float* out = (float*)d_out;

    build_idx_kernel<<<(NPOLY + 255) / 256, 256>>>();
    taylor_kernel<<<BATCH / ROWS, THREADS>>>(x, W, out);
}

// round 7
// speedup vs baseline: 1.4811x; 1.4778x over previous
#include <cuda_runtime.h>
#include <cuda_bf16.h>
#include <cstdint>

#define NF       32
#define NPOLY    6545
#define BATCH    8192
#define MTILE    128
#define NCHUNK   410          // ceil(6545/16) k16-chunks, zero-padded to 6560
#define CHALF    205          // chunks per K-split
#define THREADS  256

__device__ uint32_t           g_idx[NPOLY];
__device__ uint4              g_idxfrag[NCHUNK * 4];           // [chunk][q] -> idx of k=2q,2q+1,2q+8,2q+9
__device__ unsigned long long g_wfrag[NCHUNK * 2 * 4 * 32];    // [chunk][plane][ntile][lane] -> {reg0,reg1}
__device__ float              g_part[2][BATCH * NF];

// ---------------------------------------------------------------------------
// Monomial index decode (same mapping that passed at rel_err=1.7e-6):
// p=0 -> 1 ; [1,33): x_m ; [33,561): x_f*x_m ; [561,6545): x_f*(x_g*x_m),
// m<=g<=f triangular — reference's Pascal recursion order.
// ---------------------------------------------------------------------------
__device__ uint32_t decode_idx(int p) {
    int a = 32, b = 32, c = 32;
    if (p <= 0 || p >= NPOLY) {
        // p==0 or padded tail: value 1.0 (B is zero-padded there, so harmless)
    } else if (p < 33) {
        a = p - 1;
    } else if (p < 561) {
        int q = p - 33;
        int f = (int)((sqrtf(8.0f * (float)q + 1.0f) - 1.0f) * 0.5f);
        if (f < 0) f = 0; if (f > 31) f = 31;
        while (f < 31 && (f + 1) * (f + 2) / 2 <= q) f++;
        while (f > 0 && f * (f + 1) / 2 > q) f--;
        a = f; b = q - f * (f + 1) / 2;
    } else {
        int q = p - 561;
        int f = (int)cbrtf(6.0f * (float)q);
        if (f < 0) f = 0; if (f > 31) f = 31;
        while (f < 31 && (f + 1) * (f + 2) * (f + 3) / 6 <= q) f++;
        while (f > 0 && f * (f + 1) * (f + 2) / 6 > q) f--;
        int r = q - f * (f + 1) * (f + 2) / 6;
        int g = (int)((sqrtf(8.0f * (float)r + 1.0f) - 1.0f) * 0.5f);
        if (g < 0) g = 0; if (g > f) g = f;
        while (g < f && (g + 1) * (g + 2) / 2 <= r) g++;
        while (g > 0 && g * (g + 1) / 2 > r) g--;
        a = f; b = g; c = r - g * (g + 1) / 2;
    }
    return (uint32_t)a | ((uint32_t)b << 8) | ((uint32_t)c << 16);
}

__global__ void build_idx_kernel() {
    int p = blockIdx.x * blockDim.x + threadIdx.x;
    if (p < NPOLY) g_idx[p] = decode_idx(p);
}

// idx fragments: [chunk][q] -> uint4 {k=2q, 2q+1, 2q+8, 2q+9} (k rel. chunk*16)
__global__ void build_idxfrag_kernel() {
    int e = blockIdx.x * blockDim.x + threadIdx.x;
    if (e >= NCHUNK * 4) return;
    int c = e >> 2, q = e & 3;
    int k0 = c * 16 + 2 * q;
    uint4 v;
    v.x = (k0     < NPOLY) ? g_idx[k0]     : 0x202020u;
    v.y = (k0 + 1 < NPOLY) ? g_idx[k0 + 1] : 0x202020u;
    v.z = (k0 + 8 < NPOLY) ? g_idx[k0 + 8] : 0x202020u;
    v.w = (k0 + 9 < NPOLY) ? g_idx[k0 + 9] : 0x202020u;
    g_idxfrag[e] = v;
}

// W fragment images: for mma.m16n8k16.row.col B operand (col-major KxN):
//   lane: q=lane&3, n=ntile*8+(lane>>2)
//   reg0 = {B[2q][n], B[2q+1][n]}, reg1 = {B[2q+8][n], B[2q+9][n]}  (bf16x2, low=first)
// plane 0 = bf16 hi of W, plane 1 = bf16 of (W - hi). Tail k >= NPOLY -> 0.
__global__ void build_wfrag_kernel(const float* __restrict__ W) {
    int e = blockIdx.x * blockDim.x + threadIdx.x;
    if (e >= NCHUNK * 2 * 4 * 32) return;
    int lane = e & 31;
    int nt   = (e >> 5) & 3;
    int p    = (e >> 7) & 1;
    int c    = e >> 8;
    int q    = lane & 3;
    int n    = nt * 8 + (lane >> 2);

    unsigned long long out = 0;
#pragma unroll
    for (int half = 0; half < 2; ++half) {
        uint32_t reg = 0;
#pragma unroll
        for (int j = 0; j < 2; ++j) {
            int k = c * 16 + 2 * q + half * 8 + j;
            float w = (k < NPOLY) ? W[k * NF + n] : 0.0f;
            __nv_bfloat16 h = __float2bfloat16(w);
            __nv_bfloat16 val = (p == 0) ? h : __float2bfloat16(w - __bfloat162float(h));
            reg |= (uint32_t)__bfloat16_as_ushort(val) << (16 * j);
        }
        out |= (unsigned long long)reg << (32 * half);
    }
    g_wfrag[e] = out;
}

// ---------------------------------------------------------------------------
__device__ __forceinline__ void mma16816(float* d, const uint32_t* a,
                                         uint32_t b0, uint32_t b1) {
    asm("mma.sync.aligned.m16n8k16.row.col.f32.bf16.bf16.f32 "
        "{%0,%1,%2,%3}, {%4,%5,%6,%7}, {%8,%9}, {%0,%1,%2,%3};"
        : "+f"(d[0]), "+f"(d[1]), "+f"(d[2]), "+f"(d[3])
        : "r"(a[0]), "r"(a[1]), "r"(a[2]), "r"(a[3]), "r"(b0), "r"(b1));
}

__device__ __forceinline__ uint32_t packbf2(float lo, float hi) {
    __nv_bfloat162 t = __floats2bfloat162_rn(lo, hi);   // .x = lo half
    return *(uint32_t*)&t;
}

// ---------------------------------------------------------------------------
// Main fused kernel: CTA = 128-row M-tile x one K-half. 8 warps, each a 16-row
// stripe x full N=32 (4 n-tiles). No __syncthreads in the main loop.
// ---------------------------------------------------------------------------
__global__ __launch_bounds__(THREADS)
void taylor_mma_kernel(const float* __restrict__ x) {
    __shared__ float xt[33][136];   // bank = (8*feat + row) % 32

    const int tid   = threadIdx.x;
    const int lane  = tid & 31;
    const int warp  = tid >> 5;          // 0..7
    const int gid   = lane >> 2;         // 0..7
    const int q     = lane & 3;          // 0..3
    const int tile  = blockIdx.x >> 1;
    const int split = blockIdx.x & 1;
    const int row0  = tile * MTILE;
    const int r0    = warp * 16 + gid;   // local rows r0, r0+8
    const int r1    = r0 + 8;

    // stage x transposed (+ const-1 feature row)
    for (int e = tid; e < MTILE * NF; e += THREADS) {
        int rr = e >> 5, ii = e & 31;
        xt[ii][rr] = x[(row0 + rr) * NF + ii];
    }
    if (tid < MTILE) xt[32][tid] = 1.0f;
    __syncthreads();

    float acc[4][4];
#pragma unroll
    for (int nt = 0; nt < 4; ++nt)
#pragma unroll
        for (int j = 0; j < 4; ++j) acc[nt][j] = 0.0f;

    const int cbase = split * CHALF;
    const float* xr0 = &xt[0][r0];
    const float* xr1 = &xt[0][r1];

#pragma unroll 1
    for (int i = 0; i < CHALF; ++i) {
        const int c = cbase + i;

        // ---- loads first (LDG latency overlaps the eval chain) ----
        const uint4 id4 = g_idxfrag[c * 4 + q];
        unsigned long long Bh[4], Bl[4];
        {
            const unsigned long long* wp = &g_wfrag[(size_t)c * 256 + lane];
#pragma unroll
            for (int nt = 0; nt < 4; ++nt) {
                Bh[nt] = wp[nt * 32];
                Bl[nt] = wp[128 + nt * 32];
            }
        }

        // ---- evaluate 8 monomials (this thread's A fragment) ----
        float v0[4], v1[4];
        {
            const uint32_t ids[4] = {id4.x, id4.y, id4.z, id4.w};
#pragma unroll
            for (int j = 0; j < 4; ++j) {
                const uint32_t id = ids[j];
                const int a  = id & 255;
                const int b  = (id >> 8) & 255;
                const int cc = (id >> 16) & 255;
                v0[j] = xr0[a * 136] * (xr0[b * 136] * xr0[cc * 136]);
                v1[j] = xr1[a * 136] * (xr1[b * 136] * xr1[cc * 136]);
            }
        }

        // ---- A fragments: hi plane + residual lo plane ----
        uint32_t Ah[4], Al[4];
        Ah[0] = packbf2(v0[0], v0[1]);
        Ah[1] = packbf2(v1[0], v1[1]);
        Ah[2] = packbf2(v0[2], v0[3]);
        Ah[3] = packbf2(v1[2], v1[3]);
        {
            const float* vs[2] = {v0, v1};
#pragma unroll
            for (int rr = 0; rr < 2; ++rr) {
#pragma unroll
                for (int hh = 0; hh < 2; ++hh) {
                    uint32_t u = (rr == 0) ? Ah[hh * 2] : Ah[hh * 2 + 1];
                    float f0 = __uint_as_float(u << 16);
                    float f1 = __uint_as_float(u & 0xffff0000u);
                    float l0 = vs[rr][hh * 2]     - f0;
                    float l1 = vs[rr][hh * 2 + 1] - f1;
                    uint32_t pk = packbf2(l0, l1);
                    if (rr == 0) Al[hh * 2] = pk; else Al[hh * 2 + 1] = pk;
                }
            }
        }

        // ---- 4 n-tiles x 3 plane terms ----
#pragma unroll
        for (int nt = 0; nt < 4; ++nt) {
            uint32_t bh0 = (uint32_t)Bh[nt], bh1 = (uint32_t)(Bh[nt] >> 32);
            uint32_t bl0 = (uint32_t)Bl[nt], bl1 = (uint32_t)(Bl[nt] >> 32);
            mma16816(acc[nt], Ah, bh0, bh1);
            mma16816(acc[nt], Ah, bl0, bl1);
            mma16816(acc[nt], Al, bh0, bh1);
        }
    }

    // ---- epilogue: write partial (rows r0, r1; cols nt*8 + 2q, +1) ----
    float* dst = g_part[split];
#pragma unroll
    for (int nt = 0; nt < 4; ++nt) {
        int col = nt * 8 + 2 * q;
        *(float2*)&dst[(row0 + r0) * NF + col] = make_float2(acc[nt][0], acc[nt][1]);
        *(float2*)&dst[(row0 + r1) * NF + col] = make_float2(acc[nt][2], acc[nt][3]);
    }
}

__global__ void reduce_kernel(const float* __restrict__ x, float* __restrict__ out) {
    int i = blockIdx.x * blockDim.x + threadIdx.x;
    if (i >= BATCH * NF / 4) return;
    float4 xv = ((const float4*)x)[i];
    float4 p0 = ((const float4*)g_part[0])[i];
    float4 p1 = ((const float4*)g_part[1])[i];
    float4 o;
    o.x = xv.x + p0.x + p1.x;
    o.y = xv.y + p0.y + p1.y;
    o.z = xv.z + p0.z + p1.z;
    o.w = xv.w + p0.w + p1.w;
    ((float4*)out)[i] = o;
}

extern "C" void kernel_launch(void* const* d_in, const int* in_sizes, int n_in,
                              void* d_out, int out_size) {
    const float* x = (const float*)d_in[0];
    const float* W = (const float*)d_in[1];
    if (n_in >= 2 && in_sizes[0] == NPOLY * NF && in_sizes[1] == BATCH * NF) {
        x = (const float*)d_in[1];
        W = (const float*)d_in[0];
    }
    float* out = (float*)d_out;

    build_idx_kernel<<<(NPOLY + 255) / 256, 256>>>();
    build_idxfrag_kernel<<<(NCHUNK * 4 + 255) / 256, 256>>>();
    build_wfrag_kernel<<<(NCHUNK * 2 * 4 * 32 + 255) / 256, 256>>>(W);
    taylor_mma_kernel<<<(BATCH / MTILE) * 2, THREADS>>>(x);
    reduce_kernel<<<(BATCH * NF / 4 + 255) / 256, 256>>>(x, out);
}

// round 8
// speedup vs baseline: 4.1609x; 2.8094x over previous
#include <cuda_runtime.h>
#include <cuda_bf16.h>
#include <cstdint>

#define NF       32
#define NPOLY    6545
#define BATCH    8192
#define MTILE    128
#define NCHUNK   410          // ceil(6545/16) k16-chunks, zero-padded to 6560
#define NSPLIT   4
#define THREADS  256

__device__ uint32_t           g_idx[NPOLY];
__device__ uint4              g_idxfrag[NCHUNK * 4];           // [chunk][q] -> idx of k=2q,2q+1,2q+8,2q+9
__device__ unsigned long long g_wfrag[NCHUNK * 2 * 4 * 32];    // [chunk][plane][ntile][lane] -> {reg0,reg1}
__device__ float              g_part[NSPLIT][BATCH * NF];

// ---------------------------------------------------------------------------
// Monomial index decode: p=0 -> 1 ; [1,33): x_m ; [33,561): x_f*x_m ;
// [561,6545): x_f*(x_g*x_m), m<=g<=f triangular — reference order.
// ---------------------------------------------------------------------------
__device__ uint32_t decode_idx(int p) {
    int a = 32, b = 32, c = 32;
    if (p <= 0 || p >= NPOLY) {
    } else if (p < 33) {
        a = p - 1;
    } else if (p < 561) {
        int q = p - 33;
        int f = (int)((sqrtf(8.0f * (float)q + 1.0f) - 1.0f) * 0.5f);
        if (f < 0) f = 0; if (f > 31) f = 31;
        while (f < 31 && (f + 1) * (f + 2) / 2 <= q) f++;
        while (f > 0 && f * (f + 1) / 2 > q) f--;
        a = f; b = q - f * (f + 1) / 2;
    } else {
        int q = p - 561;
        int f = (int)cbrtf(6.0f * (float)q);
        if (f < 0) f = 0; if (f > 31) f = 31;
        while (f < 31 && (f + 1) * (f + 2) * (f + 3) / 6 <= q) f++;
        while (f > 0 && f * (f + 1) * (f + 2) / 6 > q) f--;
        int r = q - f * (f + 1) * (f + 2) / 6;
        int g = (int)((sqrtf(8.0f * (float)r + 1.0f) - 1.0f) * 0.5f);
        if (g < 0) g = 0; if (g > f) g = f;
        while (g < f && (g + 1) * (g + 2) / 2 <= r) g++;
        while (g > 0 && g * (g + 1) / 2 > r) g--;
        a = f; b = g; c = r - g * (g + 1) / 2;
    }
    return (uint32_t)a | ((uint32_t)b << 8) | ((uint32_t)c << 16);
}

__global__ void build_idx_kernel() {
    int p = blockIdx.x * blockDim.x + threadIdx.x;
    if (p < NPOLY) g_idx[p] = decode_idx(p);
}

__global__ void build_idxfrag_kernel() {
    int e = blockIdx.x * blockDim.x + threadIdx.x;
    if (e >= NCHUNK * 4) return;
    int c = e >> 2, q = e & 3;
    int k0 = c * 16 + 2 * q;
    uint4 v;
    v.x = (k0     < NPOLY) ? g_idx[k0]     : 0x202020u;
    v.y = (k0 + 1 < NPOLY) ? g_idx[k0 + 1] : 0x202020u;
    v.z = (k0 + 8 < NPOLY) ? g_idx[k0 + 8] : 0x202020u;
    v.w = (k0 + 9 < NPOLY) ? g_idx[k0 + 9] : 0x202020u;
    g_idxfrag[e] = v;
}

// W fragments for mma.m16n8k16.row.col B (col-major KxN), hi/lo bf16 planes.
__global__ void build_wfrag_kernel(const float* __restrict__ W) {
    int e = blockIdx.x * blockDim.x + threadIdx.x;
    if (e >= NCHUNK * 2 * 4 * 32) return;
    int lane = e & 31;
    int nt   = (e >> 5) & 3;
    int p    = (e >> 7) & 1;
    int c    = e >> 8;
    int q    = lane & 3;
    int n    = nt * 8 + (lane >> 2);

    unsigned long long out = 0;
#pragma unroll
    for (int half = 0; half < 2; ++half) {
        uint32_t reg = 0;
#pragma unroll
        for (int j = 0; j < 2; ++j) {
            int k = c * 16 + 2 * q + half * 8 + j;
            float w = (k < NPOLY) ? W[k * NF + n] : 0.0f;
            __nv_bfloat16 h = __float2bfloat16(w);
            __nv_bfloat16 val = (p == 0) ? h : __float2bfloat16(w - __bfloat162float(h));
            reg |= (uint32_t)__bfloat16_as_ushort(val) << (16 * j);
        }
        out |= (unsigned long long)reg << (32 * half);
    }
    g_wfrag[e] = out;
}

// ---------------------------------------------------------------------------
__device__ __forceinline__ void mma16816(float* d, const uint32_t* a,
                                         uint32_t b0, uint32_t b1) {
    asm("mma.sync.aligned.m16n8k16.row.col.f32.bf16.bf16.f32 "
        "{%0,%1,%2,%3}, {%4,%5,%6,%7}, {%8,%9}, {%0,%1,%2,%3};"
        : "+f"(d[0]), "+f"(d[1]), "+f"(d[2]), "+f"(d[3])
        : "r"(a[0]), "r"(a[1]), "r"(a[2]), "r"(a[3]), "r"(b0), "r"(b1));
}

__device__ __forceinline__ uint32_t packbf2(float lo, float hi) {
    __nv_bfloat162 t = __floats2bfloat162_rn(lo, hi);   // .x = lo half
    return *(uint32_t*)&t;
}

// ---------------------------------------------------------------------------
// Main fused kernel: CTA = 128-row M-tile x one K-quarter. 8 warps, each a
// 16-row stripe x full N=32. Register-double-buffered global loads; no
// __syncthreads in the main loop.
// ---------------------------------------------------------------------------
__global__ __launch_bounds__(THREADS)
void taylor_mma_kernel(const float* __restrict__ x) {
    __shared__ float xt[33][136];

    const int tid   = threadIdx.x;
    const int lane  = tid & 31;
    const int warp  = tid >> 5;
    const int gid   = lane >> 2;
    const int q     = lane & 3;
    const int tile  = blockIdx.x >> 2;
    const int split = blockIdx.x & 3;
    const int row0  = tile * MTILE;
    const int r0    = warp * 16 + gid;
    const int r1    = r0 + 8;

    for (int e = tid; e < MTILE * NF; e += THREADS) {
        int rr = e >> 5, ii = e & 31;
        xt[ii][rr] = x[(row0 + rr) * NF + ii];
    }
    if (tid < MTILE) xt[32][tid] = 1.0f;
    __syncthreads();

    float acc[4][4];
#pragma unroll
    for (int nt = 0; nt < 4; ++nt)
#pragma unroll
        for (int j = 0; j < 4; ++j) acc[nt][j] = 0.0f;

    // split s: base = 102*s + min(s,2), count = 102 + (s<2)
    const int cbase = 102 * split + (split < 2 ? split : 2);
    const int nch   = 102 + (split < 2 ? 1 : 0);
    const float* xr0 = &xt[0][r0];
    const float* xr1 = &xt[0][r1];

    // ---- prologue: load chunk cbase ----
    uint4 id_cur = g_idxfrag[cbase * 4 + q];
    unsigned long long Bh_cur[4], Bl_cur[4];
    {
        const unsigned long long* wp = &g_wfrag[(size_t)cbase * 256 + lane];
#pragma unroll
        for (int nt = 0; nt < 4; ++nt) {
            Bh_cur[nt] = wp[nt * 32];
            Bl_cur[nt] = wp[128 + nt * 32];
        }
    }

#pragma unroll 2
    for (int i = 0; i < nch; ++i) {
        // ---- prefetch chunk i+1 (latency overlapped with compute below) ----
        uint4 id_nxt;
        unsigned long long Bh_nxt[4], Bl_nxt[4];
        if (i + 1 < nch) {
            const int cn = cbase + i + 1;
            id_nxt = g_idxfrag[cn * 4 + q];
            const unsigned long long* wp = &g_wfrag[(size_t)cn * 256 + lane];
#pragma unroll
            for (int nt = 0; nt < 4; ++nt) {
                Bh_nxt[nt] = wp[nt * 32];
                Bl_nxt[nt] = wp[128 + nt * 32];
            }
        }

        // ---- evaluate 8 monomials ----
        float v0[4], v1[4];
        {
            const uint32_t ids[4] = {id_cur.x, id_cur.y, id_cur.z, id_cur.w};
#pragma unroll
            for (int j = 0; j < 4; ++j) {
                const uint32_t id = ids[j];
                const int a  = id & 255;
                const int b  = (id >> 8) & 255;
                const int cc = (id >> 16) & 255;
                v0[j] = xr0[a * 136] * (xr0[b * 136] * xr0[cc * 136]);
                v1[j] = xr1[a * 136] * (xr1[b * 136] * xr1[cc * 136]);
            }
        }

        // ---- A fragments: hi plane + residual lo plane ----
        uint32_t Ah[4], Al[4];
        Ah[0] = packbf2(v0[0], v0[1]);
        Ah[1] = packbf2(v1[0], v1[1]);
        Ah[2] = packbf2(v0[2], v0[3]);
        Ah[3] = packbf2(v1[2], v1[3]);
#pragma unroll
        for (int hh = 0; hh < 2; ++hh) {
            {
                uint32_t u = Ah[hh * 2];
                float f0 = __uint_as_float(u << 16);
                float f1 = __uint_as_float(u & 0xffff0000u);
                Al[hh * 2] = packbf2(v0[hh * 2] - f0, v0[hh * 2 + 1] - f1);
            }
            {
                uint32_t u = Ah[hh * 2 + 1];
                float f0 = __uint_as_float(u << 16);
                float f1 = __uint_as_float(u & 0xffff0000u);
                Al[hh * 2 + 1] = packbf2(v1[hh * 2] - f0, v1[hh * 2 + 1] - f1);
            }
        }

        // ---- 4 n-tiles x 3 plane terms ----
#pragma unroll
        for (int nt = 0; nt < 4; ++nt) {
            uint32_t bh0 = (uint32_t)Bh_cur[nt], bh1 = (uint32_t)(Bh_cur[nt] >> 32);
            uint32_t bl0 = (uint32_t)Bl_cur[nt], bl1 = (uint32_t)(Bl_cur[nt] >> 32);
            mma16816(acc[nt], Ah, bh0, bh1);
            mma16816(acc[nt], Ah, bl0, bl1);
            mma16816(acc[nt], Al, bh0, bh1);
        }

        // ---- rotate double buffer ----
        if (i + 1 < nch) {
            id_cur = id_nxt;
#pragma unroll
            for (int nt = 0; nt < 4; ++nt) {
                Bh_cur[nt] = Bh_nxt[nt];
                Bl_cur[nt] = Bl_nxt[nt];
            }
        }
    }

    // ---- epilogue: write partial ----
    float* dst = g_part[split];
#pragma unroll
    for (int nt = 0; nt < 4; ++nt) {
        int col = nt * 8 + 2 * q;
        *(float2*)&dst[(row0 + r0) * NF + col] = make_float2(acc[nt][0], acc[nt][1]);
        *(float2*)&dst[(row0 + r1) * NF + col] = make_float2(acc[nt][2], acc[nt][3]);
    }
}

__global__ void reduce_kernel(const float* __restrict__ x, float* __restrict__ out) {
    int i = blockIdx.x * blockDim.x + threadIdx.x;
    if (i >= BATCH * NF / 4) return;
    float4 xv = ((const float4*)x)[i];
    float4 p0 = ((const float4*)g_part[0])[i];
    float4 p1 = ((const float4*)g_part[1])[i];
    float4 p2 = ((const float4*)g_part[2])[i];
    float4 p3 = ((const float4*)g_part[3])[i];
    float4 o;
    o.x = xv.x + (p0.x + p1.x) + (p2.x + p3.x);
    o.y = xv.y + (p0.y + p1.y) + (p2.y + p3.y);
    o.z = xv.z + (p0.z + p1.z) + (p2.z + p3.z);
    o.w = xv.w + (p0.w + p1.w) + (p2.w + p3.w);
    ((float4*)out)[i] = o;
}

extern "C" void kernel_launch(void* const* d_in, const int* in_sizes, int n_in,
                              void* d_out, int out_size) {
    const float* x = (const float*)d_in[0];
    const float* W = (const float*)d_in[1];
    if (n_in >= 2 && in_sizes[0] == NPOLY * NF && in_sizes[1] == BATCH * NF) {
        x = (const float*)d_in[1];
        W = (const float*)d_in[0];
    }
    float* out = (float*)d_out;

    build_idx_kernel<<<(NPOLY + 255) / 256, 256>>>();
    build_idxfrag_kernel<<<(NCHUNK * 4 + 255) / 256, 256>>>();
    build_wfrag_kernel<<<(NCHUNK * 2 * 4 * 32 + 255) / 256, 256>>>(W);
    taylor_mma_kernel<<<(BATCH / MTILE) * NSPLIT, THREADS>>>(x);
    reduce_kernel<<<(BATCH * NF / 4 + 255) / 256, 256>>>(x, out);
}